// round 2
// baseline (speedup 1.0000x reference)
#include <cuda_runtime.h>
#include <math.h>

#define B 4
#define S 2048
#define E 512
#define H 8
#define D 64
#define FF 2048
#define NTOK (B*S)

// ---- device scratch (static, allocation-free) ----
__device__ float g_V[(size_t)NTOK * E];    // [b,s,h,d] token-major
__device__ float g_Q[(size_t)B * H * S];   // [b,h,s]
__device__ float g_K[(size_t)B * H * S];   // [b,h,s]
__device__ float g_HO[(size_t)NTOK * E];   // head_out [b,s,e]
__device__ float g_MID[(size_t)NTOK * FF]; // GELU(h@W1+b1)

// ============================================================
// Kernel 1: LayerNorm + per-head V (D->D), Q/K (D->1) projections
// one block per token, 256 threads
// ============================================================
__global__ __launch_bounds__(256) void ln_proj_kernel(
    const float* __restrict__ x,
    const float* __restrict__ Wv, const float* __restrict__ bv,
    const float* __restrict__ Wq, const float* __restrict__ bq,
    const float* __restrict__ Wk, const float* __restrict__ bk)
{
    __shared__ float xn[E];
    __shared__ float red[16];
    const int token = blockIdx.x;
    const int tid = threadIdx.x;
    const float* xin = x + (size_t)token * E;

    float v0 = xin[tid];
    float v1 = xin[tid + 256];
    float s = v0 + v1;
    float ss = v0 * v0 + v1 * v1;
    #pragma unroll
    for (int o = 16; o > 0; o >>= 1) {
        s  += __shfl_xor_sync(0xffffffffu, s, o);
        ss += __shfl_xor_sync(0xffffffffu, ss, o);
    }
    const int wid = tid >> 5, lid = tid & 31;
    if (lid == 0) { red[wid] = s; red[wid + 8] = ss; }
    __syncthreads();
    if (tid == 0) {
        float S1 = 0.f, S2 = 0.f;
        #pragma unroll
        for (int i = 0; i < 8; i++) { S1 += red[i]; S2 += red[i + 8]; }
        float mean = S1 * (1.0f / E);
        float var  = S2 * (1.0f / E) - mean * mean;   // population variance
        red[0] = mean;
        red[1] = rsqrtf(var + 1e-5f);
    }
    __syncthreads();
    const float mean = red[0], rstd = red[1];
    xn[tid]       = (v0 - mean) * rstd;
    xn[tid + 256] = (v1 - mean) * rstd;
    __syncthreads();

    // V projection: V[token, e] = sum_i xn[h*64+i] * Wv[h, i, d] + bv[h, d]
    float* vout = g_V + (size_t)token * E;
    #pragma unroll
    for (int rep = 0; rep < 2; rep++) {
        const int e = tid + rep * 256;
        const int h = e >> 6, d = e & 63;
        const float* w  = Wv + h * D * D + d;   // stride D over i
        const float* xh = xn + h * D;
        float acc = bv[e];
        #pragma unroll
        for (int i = 0; i < D; i++) acc = fmaf(xh[i], w[i * D], acc);
        vout[e] = acc;
    }

    // Q / K scalar projections (threads 0..15)
    if (tid < 2 * H) {
        const int h = tid & 7;
        const bool isQ = tid < H;
        const float* w  = (isQ ? Wq : Wk) + h * D;
        const float* xh = xn + h * D;
        float acc = isQ ? bq[h] : bk[h];
        #pragma unroll
        for (int i = 0; i < D; i++) acc = fmaf(xh[i], w[i], acc);
        const int b = token >> 11, sidx = token & (S - 1);
        float* dst = isQ ? g_Q : g_K;
        dst[((size_t)b * H + h) * S + sidx] = acc;
    }
}

// ============================================================
// Kernel 2: attention.  scores s = -(Q-K)^2/8 <= 0, so softmax
// with fixed m=0 is numerically safe: single streaming pass.
// grid (S/QT, B*H), 256 threads: 32 queries x 8 dim-groups.
// ============================================================
#define QT 32
#define KT 64

__global__ __launch_bounds__(256) void attn_kernel()
{
    __shared__ float Ksh[S];          // 8 KB
    __shared__ float Vsh[KT][D];      // 16 KB
    const int bh = blockIdx.y;
    const int b = bh >> 3, h = bh & 7;
    const int q0 = blockIdx.x * QT;
    const int tid = threadIdx.x;

    for (int i = tid; i < S; i += 256) Ksh[i] = g_K[(size_t)bh * S + i];

    const int ql = tid & 31;          // query within tile
    const int dg = tid >> 5;          // dim group (8 dims)
    const float q = g_Q[(size_t)bh * S + q0 + ql];

    float acc[8] = {0.f, 0.f, 0.f, 0.f, 0.f, 0.f, 0.f, 0.f};
    float den = 0.f;

    const float* Vbase = g_V + (size_t)b * S * E + h * D;  // element (s,d) at Vbase[s*E+d]

    for (int kc = 0; kc < S; kc += KT) {
        __syncthreads();
        // load V chunk [KT][64] (float4 coalesced)
        for (int i = tid; i < KT * 16; i += 256) {
            const int kk = i >> 4;
            const int d4 = (i & 15) << 2;
            *(float4*)&Vsh[kk][d4] =
                *(const float4*)&Vbase[(size_t)(kc + kk) * E + d4];
        }
        __syncthreads();
        #pragma unroll 4
        for (int kk = 0; kk < KT; kk++) {
            const float dq = q - Ksh[kc + kk];
            const float w = __expf(-0.125f * dq * dq);
            den += w;
            const float4 a = *(const float4*)&Vsh[kk][dg * 8];
            const float4 c = *(const float4*)&Vsh[kk][dg * 8 + 4];
            acc[0] = fmaf(w, a.x, acc[0]);
            acc[1] = fmaf(w, a.y, acc[1]);
            acc[2] = fmaf(w, a.z, acc[2]);
            acc[3] = fmaf(w, a.w, acc[3]);
            acc[4] = fmaf(w, c.x, acc[4]);
            acc[5] = fmaf(w, c.y, acc[5]);
            acc[6] = fmaf(w, c.z, acc[6]);
            acc[7] = fmaf(w, c.w, acc[7]);
        }
    }

    const float inv = 1.0f / den;
    float* o = g_HO + ((size_t)b * S + q0 + ql) * E + h * D + dg * 8;
    float4 r0, r1;
    r0.x = acc[0] * inv; r0.y = acc[1] * inv; r0.z = acc[2] * inv; r0.w = acc[3] * inv;
    r1.x = acc[4] * inv; r1.y = acc[5] * inv; r1.z = acc[6] * inv; r1.w = acc[7] * inv;
    *(float4*)o       = r0;
    *(float4*)(o + 4) = r1;
}

// ============================================================
// Kernel 3/4: 128x128x8 register-tiled SGEMM, 256 threads, 8x8/thread
// MODE 0: A=g_HO, C=g_MID, epilogue = GELU(x) = x*Phi(x), bias b1
// MODE 1: A=g_MID, C=out,  epilogue = +b2 + residual input1
// ============================================================
template<int MODE>
__global__ __launch_bounds__(256) void gemm_kernel(
    const float* __restrict__ Bmat, const float* __restrict__ bias,
    const float* __restrict__ res, float* __restrict__ Cout,
    int M, int N, int K)
{
    const int BM = 128, BN = 128, BK = 8;
    __shared__ float As[BK][BM];
    __shared__ float Bs[BK][BN];

    const float* A = (MODE == 0) ? g_HO : g_MID;
    float* C = (MODE == 0) ? g_MID : Cout;

    const int tid = threadIdx.x;
    const int bm = blockIdx.y * BM;
    const int bn = blockIdx.x * BN;
    const int tx = tid & 15;   // n-direction
    const int ty = tid >> 4;   // m-direction

    float acc[8][8];
    #pragma unroll
    for (int i = 0; i < 8; i++)
        #pragma unroll
        for (int j = 0; j < 8; j++) acc[i][j] = 0.f;

    // A tile loader: 128 rows x 8 K; float4 along K: row=tid>>1, kc=(tid&1)*4
    const int arow = tid >> 1, acol = (tid & 1) * 4;
    // B tile loader: 8 K x 128 N; float4 along N: krow=tid>>5, ncol=(tid&31)*4
    const int brow = tid >> 5, bcol = (tid & 31) * 4;

    const float* Aptr = A + (size_t)(bm + arow) * K + acol;
    const float* Bptr = Bmat + (size_t)brow * N + bn + bcol;

    for (int k0 = 0; k0 < K; k0 += BK) {
        const float4 a4 = *(const float4*)(Aptr + k0);
        const float4 b4 = *(const float4*)(Bptr + (size_t)k0 * N);
        __syncthreads();
        As[acol + 0][arow] = a4.x;
        As[acol + 1][arow] = a4.y;
        As[acol + 2][arow] = a4.z;
        As[acol + 3][arow] = a4.w;
        *(float4*)&Bs[brow][bcol] = b4;
        __syncthreads();
        #pragma unroll
        for (int k = 0; k < BK; k++) {
            float ra[8], rb[8];
            #pragma unroll
            for (int i = 0; i < 8; i++) ra[i] = As[k][ty * 8 + i];
            #pragma unroll
            for (int j = 0; j < 8; j++) rb[j] = Bs[k][tx * 8 + j];
            #pragma unroll
            for (int i = 0; i < 8; i++)
                #pragma unroll
                for (int j = 0; j < 8; j++)
                    acc[i][j] = fmaf(ra[i], rb[j], acc[i][j]);
        }
    }

    // epilogue
    #pragma unroll
    for (int i = 0; i < 8; i++) {
        const int row = bm + ty * 8 + i;
        const size_t base = (size_t)row * N + bn + tx * 8;
        #pragma unroll
        for (int j0 = 0; j0 < 8; j0 += 4) {
            float4 v;
            float tmp[4];
            #pragma unroll
            for (int l = 0; l < 4; l++) {
                float c = acc[i][j0 + l] + bias[bn + tx * 8 + j0 + l];
                if (MODE == 0) {
                    c = c * normcdff(c);           // exact GELU
                } else {
                    c += res[base + j0 + l];       // + input1 residual
                }
                tmp[l] = c;
            }
            v.x = tmp[0]; v.y = tmp[1]; v.z = tmp[2]; v.w = tmp[3];
            *(float4*)&C[base + j0] = v;
        }
    }
}

// ============================================================
extern "C" void kernel_launch(void* const* d_in, const int* in_sizes, int n_in,
                              void* d_out, int out_size)
{
    const float* input1 = (const float*)d_in[0];
    const float* Wv = (const float*)d_in[1];
    const float* bv = (const float*)d_in[2];
    const float* Wq = (const float*)d_in[3];
    const float* bq = (const float*)d_in[4];
    const float* Wk = (const float*)d_in[5];
    const float* bk = (const float*)d_in[6];
    const float* W1 = (const float*)d_in[7];
    const float* b1 = (const float*)d_in[8];
    const float* W2 = (const float*)d_in[9];
    const float* b2 = (const float*)d_in[10];
    float* out = (float*)d_out;

    ln_proj_kernel<<<NTOK, 256>>>(input1, Wv, bv, Wq, bq, Wk, bk);
    attn_kernel<<<dim3(S / QT, B * H), 256>>>();
    gemm_kernel<0><<<dim3(FF / 128, NTOK / 128), 256>>>(W1, b1, nullptr, nullptr, NTOK, FF, E);
    gemm_kernel<1><<<dim3(E / 128, NTOK / 128), 256>>>(W2, b2, input1, out, NTOK, E, FF);
}

// round 4
// speedup vs baseline: 2.9754x; 2.9754x over previous
#include <cuda_runtime.h>
#include <math.h>
#include <stdint.h>

#define B 4
#define S 2048
#define E 512
#define H 8
#define D 64
#define FF 2048
#define NTOK (B*S)

// ---- device scratch (static, allocation-free) ----
__device__ float g_V[(size_t)NTOK * E];     // [b,s,h,d] token-major, tf32-rounded
__device__ float g_Q[(size_t)B * H * S];    // [b,h,s]
__device__ float g_K[(size_t)B * H * S];    // [b,h,s]
__device__ float g_HO[(size_t)NTOK * E];    // head_out [b,s,e], tf32-rounded
__device__ float g_MID[(size_t)NTOK * FF];  // GELU(h@W1+b1), tf32-rounded
__device__ float g_Wt1[(size_t)FF * E];     // W1^T [N=FF][K=E], tf32-rounded
__device__ float g_Wt2[(size_t)E * FF];     // W2^T [N=E][K=FF], tf32-rounded

// ============================================================
// Helpers (arch-generic PTX only: mma.sync / cp.async — no 'a' features)
// ============================================================
__device__ __forceinline__ uint32_t smem_u32(const void* p) {
    uint32_t a;
    asm("{ .reg .u64 t; cvta.to.shared.u64 t, %1; cvt.u32.u64 %0, t; }" : "=r"(a) : "l"(p));
    return a;
}
__device__ __forceinline__ float round_tf32(float x) {
    uint32_t u;
    asm("cvt.rna.tf32.f32 %0, %1;" : "=r"(u) : "f"(x));
    return __uint_as_float(u);
}
#define CP_ASYNC16(dst, src) \
    asm volatile("cp.async.cg.shared.global [%0], [%1], 16;" :: "r"(dst), "l"(src) : "memory")
#define CP_COMMIT() asm volatile("cp.async.commit_group;" ::: "memory")
template<int N> __device__ __forceinline__ void cp_wait() {
    asm volatile("cp.async.wait_group %0;" :: "n"(N) : "memory");
}

// m16n8k8 tf32 mma: C += A*B ; A row-major frag (4 regs), B col-major frag (2 regs)
__device__ __forceinline__ void mma_tf32(float* c, const uint32_t* a, const uint32_t* b) {
    asm volatile(
        "mma.sync.aligned.m16n8k8.row.col.f32.tf32.tf32.f32 "
        "{%0,%1,%2,%3}, {%4,%5,%6,%7}, {%8,%9}, {%0,%1,%2,%3};"
        : "+f"(c[0]), "+f"(c[1]), "+f"(c[2]), "+f"(c[3])
        : "r"(a[0]), "r"(a[1]), "r"(a[2]), "r"(a[3]), "r"(b[0]), "r"(b[1]));
}

// ============================================================
// Kernel 0: weight transpose + tf32 round: W[K][N] -> Wt[N][K]
// ============================================================
__global__ __launch_bounds__(256) void transpose_round_kernel(
    const float* __restrict__ W, float* __restrict__ Wt, int K, int N)
{
    __shared__ float t[32][33];
    const int n0 = blockIdx.x * 32;
    const int k0 = blockIdx.y * 32;
    const int tx = threadIdx.x & 31;
    const int ty = threadIdx.x >> 5;   // 0..7
    #pragma unroll
    for (int r = 0; r < 4; r++) {
        const int k = k0 + ty + r * 8;
        t[ty + r * 8][tx] = round_tf32(W[(size_t)k * N + n0 + tx]);
    }
    __syncthreads();
    #pragma unroll
    for (int r = 0; r < 4; r++) {
        const int n = n0 + ty + r * 8;
        Wt[(size_t)n * K + k0 + tx] = t[tx][ty + r * 8];
    }
}

// ============================================================
// Kernel 1: LayerNorm + per-head V (D->D), Q/K (D->1) projections
// V output tf32-rounded (it feeds the attention mma as B operand).
// ============================================================
__global__ __launch_bounds__(256) void ln_proj_kernel(
    const float* __restrict__ x,
    const float* __restrict__ Wv, const float* __restrict__ bv,
    const float* __restrict__ Wq, const float* __restrict__ bq,
    const float* __restrict__ Wk, const float* __restrict__ bk)
{
    __shared__ float xn[E];
    __shared__ float red[16];
    const int token = blockIdx.x;
    const int tid = threadIdx.x;
    const float* xin = x + (size_t)token * E;

    float v0 = xin[tid];
    float v1 = xin[tid + 256];
    float s = v0 + v1;
    float ss = v0 * v0 + v1 * v1;
    #pragma unroll
    for (int o = 16; o > 0; o >>= 1) {
        s  += __shfl_xor_sync(0xffffffffu, s, o);
        ss += __shfl_xor_sync(0xffffffffu, ss, o);
    }
    const int wid = tid >> 5, lid = tid & 31;
    if (lid == 0) { red[wid] = s; red[wid + 8] = ss; }
    __syncthreads();
    if (tid == 0) {
        float S1 = 0.f, S2 = 0.f;
        #pragma unroll
        for (int i = 0; i < 8; i++) { S1 += red[i]; S2 += red[i + 8]; }
        float mean = S1 * (1.0f / E);
        float var  = S2 * (1.0f / E) - mean * mean;
        red[0] = mean;
        red[1] = rsqrtf(var + 1e-5f);
    }
    __syncthreads();
    const float mean = red[0], rstd = red[1];
    xn[tid]       = (v0 - mean) * rstd;
    xn[tid + 256] = (v1 - mean) * rstd;
    __syncthreads();

    float* vout = g_V + (size_t)token * E;
    #pragma unroll
    for (int rep = 0; rep < 2; rep++) {
        const int e = tid + rep * 256;
        const int h = e >> 6, d = e & 63;
        const float* w  = Wv + h * D * D + d;
        const float* xh = xn + h * D;
        float acc = bv[e];
        #pragma unroll
        for (int i = 0; i < D; i++) acc = fmaf(xh[i], w[i * D], acc);
        vout[e] = round_tf32(acc);
    }

    if (tid < 2 * H) {
        const int h = tid & 7;
        const bool isQ = tid < H;
        const float* w  = (isQ ? Wq : Wk) + h * D;
        const float* xh = xn + h * D;
        float acc = isQ ? bq[h] : bk[h];
        #pragma unroll
        for (int i = 0; i < D; i++) acc = fmaf(xh[i], w[i], acc);
        const int b = token >> 11, sidx = token & (S - 1);
        float* dst = isQ ? g_Q : g_K;
        dst[((size_t)b * H + h) * S + sidx] = acc;
    }
}

// ============================================================
// Kernel 2: attention via mma.sync.
// Per CTA: one (b,h), 64 queries. Stream K in 64-key chunks:
//   P[64q][64k] = tf32(exp(-(Q-K)^2/8))  (scores <= 0 -> m=0 softmax safe)
//   O += P @ V  via m16n8k8 tf32 mma; den = fp32 row-sum of the same tf32 w.
// 256 threads = 8 warps as 4(m) x 2(n): warp tile 16q x 32d.
// smem (floats): Ksh[2048] | den[64] | denp[256] | Ps[64][68] | Vs[2][64][72]
// ============================================================
#define ATT_SMEM_FLOATS (2048 + 64 + 256 + 64*68 + 2*64*72)
#define ATT_SMEM_BYTES  (ATT_SMEM_FLOATS * 4)

__global__ __launch_bounds__(256) void attn_kernel()
{
    extern __shared__ float smem[];
    float* Ksh   = smem;                 // 2048
    float* den_s = smem + 2048;          // 64
    float* denp  = smem + 2112;          // 256
    float* Ps    = smem + 2368;          // 64*68   (byte off 9472, 16B aligned)
    float* Vs    = smem + 6720;          // 2*64*72 (byte off 26880, 16B aligned)

    const int bh = blockIdx.y;
    const int b = bh >> 3, h = bh & 7;
    const int q0 = blockIdx.x * 64;
    const int tid = threadIdx.x;
    const int lane = tid & 31, wid = tid >> 5;
    const uint32_t sbase = smem_u32(smem);
    const uint32_t vs_off = 6720u * 4u;

    for (int i = tid; i < S; i += 256) Ksh[i] = g_K[(size_t)bh * S + i];

    const int ql = tid >> 2;             // query owned for P-gen (0..63)
    const int km = tid & 3;              // k-mod-4 lane for P-gen
    const float qv = g_Q[(size_t)bh * S + q0 + ql];
    float dpart = 0.f;

    const float* Vg = g_V + (size_t)b * S * E + h * D;

    auto loadV = [&](int kc, int buf) {
        #pragma unroll
        for (int p = 0; p < 4; p++) {
            const int r = (tid >> 4) + p * 16;
            const float* src = Vg + (size_t)(kc * 64 + r) * E + (tid & 15) * 4;
            const uint32_t dst = sbase + vs_off +
                (uint32_t)((buf * 4608 + r * 72 + (tid & 15) * 4) * 4);
            CP_ASYNC16(dst, src);
        }
    };

    loadV(0, 0);
    CP_COMMIT();
    __syncthreads();    // Ksh ready

    const int wm = wid >> 1;   // 0..3 -> q rows wm*16
    const int wn = wid & 1;    // 0..1 -> d cols wn*32
    float acc[4][4];
    #pragma unroll
    for (int i = 0; i < 4; i++)
        #pragma unroll
        for (int j = 0; j < 4; j++) acc[i][j] = 0.f;

    const int NCH = S / 64;    // 32
    for (int kc = 0; kc < NCH; kc++) {
        const int buf = kc & 1;
        if (kc + 1 < NCH) { loadV(kc + 1, buf ^ 1); CP_COMMIT(); }
        // ---- P generation (independent of V arrival) ----
        #pragma unroll
        for (int i = 0; i < 16; i++) {
            const int kk = km + i * 4;
            const float d = qv - Ksh[kc * 64 + kk];
            float w = __expf(-0.125f * d * d);
            w = round_tf32(w);
            dpart += w;
            Ps[ql * 68 + kk] = w;
        }
        if (kc + 1 < NCH) cp_wait<1>(); else cp_wait<0>();
        __syncthreads();
        // ---- O += P @ V ----
        const uint32_t* Pu = (const uint32_t*)Ps;
        const uint32_t* Vu = (const uint32_t*)(Vs + buf * 4608);
        #pragma unroll
        for (int ks = 0; ks < 8; ks++) {
            const int k0 = ks * 8 + (lane & 3);
            const int r0 = wm * 16 + (lane >> 2);
            uint32_t a[4];
            a[0] = Pu[r0 * 68 + k0];
            a[1] = Pu[(r0 + 8) * 68 + k0];
            a[2] = Pu[r0 * 68 + k0 + 4];
            a[3] = Pu[(r0 + 8) * 68 + k0 + 4];
            #pragma unroll
            for (int nt = 0; nt < 4; nt++) {
                const int n0 = wn * 32 + nt * 8 + (lane >> 2);
                uint32_t bb[2] = { Vu[k0 * 72 + n0], Vu[(k0 + 4) * 72 + n0] };
                mma_tf32(acc[nt], a, bb);
            }
        }
        __syncthreads();
    }

    // denominator reduce: 4 partials per query
    denp[tid] = dpart;
    __syncthreads();
    if (tid < 64) {
        float s4 = denp[tid * 4] + denp[tid * 4 + 1] + denp[tid * 4 + 2] + denp[tid * 4 + 3];
        den_s[tid] = 1.0f / s4;
    }
    __syncthreads();

    // epilogue: normalize, tf32-round, store to g_HO
    const int r0 = wm * 16 + (lane >> 2);
    const float inv0 = den_s[r0], inv1 = den_s[r0 + 8];
    #pragma unroll
    for (int nt = 0; nt < 4; nt++) {
        const int col = wn * 32 + nt * 8 + (lane & 3) * 2;
        float2 v0, v1;
        v0.x = round_tf32(acc[nt][0] * inv0);
        v0.y = round_tf32(acc[nt][1] * inv0);
        v1.x = round_tf32(acc[nt][2] * inv1);
        v1.y = round_tf32(acc[nt][3] * inv1);
        const size_t t0 = ((size_t)b * S + q0 + r0) * E + h * D + col;
        const size_t t1 = ((size_t)b * S + q0 + r0 + 8) * E + h * D + col;
        *(float2*)&g_HO[t0] = v0;
        *(float2*)&g_HO[t1] = v1;
    }
}

// ============================================================
// Kernel 3/4: mma.sync tf32 GEMM. 128x128 CTA tile, BK=32, 3-stage cp.async.
// A[M][K] row-major (pre-rounded tf32), Bt[N][K] row-major (pre-rounded).
// 256 threads = 8 warps as 2(m) x 4(n): warp tile 64m x 32n.
// smem: 3 stages x (A[128][32] + B[128][32]) swizzled: elem (r,k) at
//   r*32 + (k ^ ((r&7)<<2))  -> conflict-free frag loads AND cp.async stores.
// MODE 0: C=g_MID, epilogue = tf32(GELU(x+b1))
// MODE 1: C=out,   epilogue = x + b2 + input1
// ============================================================
#define GEMM_SMEM_BYTES (3 * 8192 * 4)   // 98304

template<int MODE>
__global__ __launch_bounds__(256) void tc_gemm_kernel(
    const float* __restrict__ Bt, const float* __restrict__ bias,
    const float* __restrict__ res, float* __restrict__ Cout,
    int N, int K)
{
    extern __shared__ float smem[];
    const float* A = (MODE == 0) ? g_HO : g_MID;
    float* C = (MODE == 0) ? g_MID : Cout;

    const int tid = threadIdx.x;
    const int lane = tid & 31, wid = tid >> 5;
    const int bm = blockIdx.y * 128;
    const int bn = blockIdx.x * 128;
    const int wm = wid >> 2;   // 0..1 -> rows wm*64
    const int wn = wid & 3;    // 0..3 -> cols wn*32
    const uint32_t sbase = smem_u32(smem);

    const int lr = tid >> 3;   // loader row base (0..31)
    const int lg = tid & 7;    // loader k-group (float4)

    auto load_tile = [&](int kc, int st) {
        #pragma unroll
        for (int p = 0; p < 4; p++) {
            const int r = lr + p * 32;
            const uint32_t sw = (uint32_t)((st * 8192 + r * 32 + ((lg ^ (r & 7)) * 4)) * 4);
            const float* asrc = A  + (size_t)(bm + r) * K + kc * 32 + lg * 4;
            const float* bsrc = Bt + (size_t)(bn + r) * K + kc * 32 + lg * 4;
            CP_ASYNC16(sbase + sw, asrc);
            CP_ASYNC16(sbase + sw + 4096u * 4u, bsrc);
        }
    };

    float acc[4][4][4];
    #pragma unroll
    for (int i = 0; i < 4; i++)
        #pragma unroll
        for (int j = 0; j < 4; j++)
            #pragma unroll
            for (int l = 0; l < 4; l++) acc[i][j][l] = 0.f;

    const int nc = K / 32;
    load_tile(0, 0); CP_COMMIT();
    load_tile(1, 1); CP_COMMIT();

    for (int kc = 0; kc < nc; kc++) {
        const int st = kc % 3;
        if (kc + 2 < nc) { load_tile(kc + 2, (kc + 2) % 3); CP_COMMIT(); cp_wait<2>(); }
        else if (kc + 1 < nc) cp_wait<1>();
        else cp_wait<0>();
        __syncthreads();

        const uint32_t* As = (const uint32_t*)smem + st * 8192;
        const uint32_t* Bs = As + 4096;
        #pragma unroll
        for (int ks = 0; ks < 4; ks++) {
            const int k0 = ks * 8 + (lane & 3);
            uint32_t a[4][4], bb[4][2];
            #pragma unroll
            for (int mt = 0; mt < 4; mt++) {
                const int r0 = wm * 64 + mt * 16 + (lane >> 2);
                const int sw = (r0 & 7) << 2;
                a[mt][0] = As[r0 * 32 + (k0 ^ sw)];
                a[mt][1] = As[(r0 + 8) * 32 + (k0 ^ sw)];
                a[mt][2] = As[r0 * 32 + ((k0 + 4) ^ sw)];
                a[mt][3] = As[(r0 + 8) * 32 + ((k0 + 4) ^ sw)];
            }
            #pragma unroll
            for (int nt = 0; nt < 4; nt++) {
                const int n0 = wn * 32 + nt * 8 + (lane >> 2);
                const int sw = (n0 & 7) << 2;
                bb[nt][0] = Bs[n0 * 32 + (k0 ^ sw)];
                bb[nt][1] = Bs[n0 * 32 + ((k0 + 4) ^ sw)];
            }
            #pragma unroll
            for (int mt = 0; mt < 4; mt++)
                #pragma unroll
                for (int nt = 0; nt < 4; nt++)
                    mma_tf32(acc[mt][nt], a[mt], bb[nt]);
        }
        __syncthreads();
    }

    // epilogue: float2 stores; bias from global (L2-resident)
    #pragma unroll
    for (int mt = 0; mt < 4; mt++) {
        const int r0 = bm + wm * 64 + mt * 16 + (lane >> 2);
        #pragma unroll
        for (int nt = 0; nt < 4; nt++) {
            const int col = bn + wn * 32 + nt * 8 + (lane & 3) * 2;
            const float bz0 = bias[col], bz1 = bias[col + 1];
            float c0 = acc[mt][nt][0] + bz0;
            float c1 = acc[mt][nt][1] + bz1;
            float c2 = acc[mt][nt][2] + bz0;
            float c3 = acc[mt][nt][3] + bz1;
            const size_t g0 = (size_t)r0 * N + col;
            const size_t g1 = (size_t)(r0 + 8) * N + col;
            if (MODE == 0) {
                c0 = round_tf32(c0 * normcdff(c0));
                c1 = round_tf32(c1 * normcdff(c1));
                c2 = round_tf32(c2 * normcdff(c2));
                c3 = round_tf32(c3 * normcdff(c3));
            } else {
                c0 += res[g0]; c1 += res[g0 + 1];
                c2 += res[g1]; c3 += res[g1 + 1];
            }
            float2 v0; v0.x = c0; v0.y = c1;
            float2 v1; v1.x = c2; v1.y = c3;
            *(float2*)&C[g0] = v0;
            *(float2*)&C[g1] = v1;
        }
    }
}

// ============================================================
extern "C" void kernel_launch(void* const* d_in, const int* in_sizes, int n_in,
                              void* d_out, int out_size)
{
    const float* input1 = (const float*)d_in[0];
    const float* Wv = (const float*)d_in[1];
    const float* bv = (const float*)d_in[2];
    const float* Wq = (const float*)d_in[3];
    const float* bq = (const float*)d_in[4];
    const float* Wk = (const float*)d_in[5];
    const float* bk = (const float*)d_in[6];
    const float* W1 = (const float*)d_in[7];
    const float* b1 = (const float*)d_in[8];
    const float* W2 = (const float*)d_in[9];
    const float* b2 = (const float*)d_in[10];
    float* out = (float*)d_out;

    float* s_Wt1; cudaGetSymbolAddress((void**)&s_Wt1, g_Wt1);
    float* s_Wt2; cudaGetSymbolAddress((void**)&s_Wt2, g_Wt2);

    cudaFuncSetAttribute(attn_kernel, cudaFuncAttributeMaxDynamicSharedMemorySize, ATT_SMEM_BYTES);
    cudaFuncSetAttribute(tc_gemm_kernel<0>, cudaFuncAttributeMaxDynamicSharedMemorySize, GEMM_SMEM_BYTES);
    cudaFuncSetAttribute(tc_gemm_kernel<1>, cudaFuncAttributeMaxDynamicSharedMemorySize, GEMM_SMEM_BYTES);

    // weight transposes (independent of activations)
    transpose_round_kernel<<<dim3(FF / 32, E / 32), 256>>>(W1, s_Wt1, E, FF);
    transpose_round_kernel<<<dim3(E / 32, FF / 32), 256>>>(W2, s_Wt2, FF, E);

    ln_proj_kernel<<<NTOK, 256>>>(input1, Wv, bv, Wq, bq, Wk, bk);
    attn_kernel<<<dim3(S / 64, B * H), 256, ATT_SMEM_BYTES>>>();

    tc_gemm_kernel<0><<<dim3(FF / 128, NTOK / 128), 256, GEMM_SMEM_BYTES>>>(s_Wt1, b1, nullptr, nullptr, FF, E);
    tc_gemm_kernel<1><<<dim3(E / 128, NTOK / 128), 256, GEMM_SMEM_BYTES>>>(s_Wt2, b2, input1, out, E, FF);
}

// round 5
// speedup vs baseline: 3.2141x; 1.0802x over previous
#include <cuda_runtime.h>
#include <math.h>
#include <stdint.h>

#define B 4
#define S 2048
#define E 512
#define H 8
#define D 64
#define FF 2048
#define NTOK (B*S)

// ---- device scratch (static, allocation-free) ----
__device__ float g_V[(size_t)NTOK * E];     // [b,s,h,d] token-major, tf32-rounded
__device__ float g_Q[(size_t)B * H * S];    // [b,h,s]
__device__ float g_K[(size_t)B * H * S];    // [b,h,s]
__device__ float g_HO[(size_t)NTOK * E];    // head_out [b,s,e], tf32-rounded
__device__ float g_MID[(size_t)NTOK * FF];  // GELU(h@W1+b1), tf32-rounded
__device__ float g_Wt1[(size_t)FF * E];     // W1^T [N=FF][K=E], tf32-rounded
__device__ float g_Wt2[(size_t)E * FF];     // W2^T [N=E][K=FF], tf32-rounded

// ============================================================
// Helpers (arch-generic PTX: mma.sync / cp.async / ldmatrix)
// ============================================================
__device__ __forceinline__ uint32_t smem_u32(const void* p) {
    uint32_t a;
    asm("{ .reg .u64 t; cvta.to.shared.u64 t, %1; cvt.u32.u64 %0, t; }" : "=r"(a) : "l"(p));
    return a;
}
__device__ __forceinline__ float round_tf32(float x) {
    uint32_t u;
    asm("cvt.rna.tf32.f32 %0, %1;" : "=r"(u) : "f"(x));
    return __uint_as_float(u);
}
#define CP_ASYNC16(dst, src) \
    asm volatile("cp.async.cg.shared.global [%0], [%1], 16;" :: "r"(dst), "l"(src) : "memory")
#define CP_COMMIT() asm volatile("cp.async.commit_group;" ::: "memory")
template<int N> __device__ __forceinline__ void cp_wait() {
    asm volatile("cp.async.wait_group %0;" :: "n"(N) : "memory");
}
// m16n8k8 tf32 mma
__device__ __forceinline__ void mma_tf32(float* c, const uint32_t* a, const uint32_t* b) {
    asm volatile(
        "mma.sync.aligned.m16n8k8.row.col.f32.tf32.tf32.f32 "
        "{%0,%1,%2,%3}, {%4,%5,%6,%7}, {%8,%9}, {%0,%1,%2,%3};"
        : "+f"(c[0]), "+f"(c[1]), "+f"(c[2]), "+f"(c[3])
        : "r"(a[0]), "r"(a[1]), "r"(a[2]), "r"(a[3]), "r"(b[0]), "r"(b[1]));
}
// ldmatrix x4 (b32-as-b16 trick: each matrix = 8 rows x 16B)
__device__ __forceinline__ void ldsm_x4(uint32_t* r, uint32_t addr) {
    asm volatile("ldmatrix.sync.aligned.m8n8.x4.shared.b16 {%0,%1,%2,%3}, [%4];"
        : "=r"(r[0]), "=r"(r[1]), "=r"(r[2]), "=r"(r[3]) : "r"(addr));
}

// ============================================================
// Kernel 0: weight transpose + tf32 round: W[K][N] -> Wt[N][K]
// ============================================================
__global__ __launch_bounds__(256) void transpose_round_kernel(
    const float* __restrict__ W, float* __restrict__ Wt, int K, int N)
{
    __shared__ float t[32][33];
    const int n0 = blockIdx.x * 32;
    const int k0 = blockIdx.y * 32;
    const int tx = threadIdx.x & 31;
    const int ty = threadIdx.x >> 5;
    #pragma unroll
    for (int r = 0; r < 4; r++)
        t[ty + r * 8][tx] = round_tf32(W[(size_t)(k0 + ty + r * 8) * N + n0 + tx]);
    __syncthreads();
    #pragma unroll
    for (int r = 0; r < 4; r++)
        Wt[(size_t)(n0 + ty + r * 8) * K + k0 + tx] = t[tx][ty + r * 8];
}

// ============================================================
// Kernel 1: LayerNorm + per-head V (D->D), Q/K (D->1) projections
// ============================================================
__global__ __launch_bounds__(256) void ln_proj_kernel(
    const float* __restrict__ x,
    const float* __restrict__ Wv, const float* __restrict__ bv,
    const float* __restrict__ Wq, const float* __restrict__ bq,
    const float* __restrict__ Wk, const float* __restrict__ bk)
{
    __shared__ float xn[E];
    __shared__ float red[16];
    const int token = blockIdx.x;
    const int tid = threadIdx.x;
    const float* xin = x + (size_t)token * E;

    float v0 = xin[tid];
    float v1 = xin[tid + 256];
    float s = v0 + v1;
    float ss = v0 * v0 + v1 * v1;
    #pragma unroll
    for (int o = 16; o > 0; o >>= 1) {
        s  += __shfl_xor_sync(0xffffffffu, s, o);
        ss += __shfl_xor_sync(0xffffffffu, ss, o);
    }
    const int wid = tid >> 5, lid = tid & 31;
    if (lid == 0) { red[wid] = s; red[wid + 8] = ss; }
    __syncthreads();
    if (tid == 0) {
        float S1 = 0.f, S2 = 0.f;
        #pragma unroll
        for (int i = 0; i < 8; i++) { S1 += red[i]; S2 += red[i + 8]; }
        float mean = S1 * (1.0f / E);
        float var  = S2 * (1.0f / E) - mean * mean;
        red[0] = mean;
        red[1] = rsqrtf(var + 1e-5f);
    }
    __syncthreads();
    const float mean = red[0], rstd = red[1];
    xn[tid]       = (v0 - mean) * rstd;
    xn[tid + 256] = (v1 - mean) * rstd;
    __syncthreads();

    float* vout = g_V + (size_t)token * E;
    #pragma unroll
    for (int rep = 0; rep < 2; rep++) {
        const int e = tid + rep * 256;
        const int h = e >> 6, d = e & 63;
        const float* w  = Wv + h * D * D + d;
        const float* xh = xn + h * D;
        float acc = bv[e];
        #pragma unroll
        for (int i = 0; i < D; i++) acc = fmaf(xh[i], w[i * D], acc);
        vout[e] = round_tf32(acc);
    }

    if (tid < 2 * H) {
        const int h = tid & 7;
        const bool isQ = tid < H;
        const float* w  = (isQ ? Wq : Wk) + h * D;
        const float* xh = xn + h * D;
        float acc = isQ ? bq[h] : bk[h];
        #pragma unroll
        for (int i = 0; i < D; i++) acc = fmaf(xh[i], w[i], acc);
        const int b = token >> 11, sidx = token & (S - 1);
        float* dst = isQ ? g_Q : g_K;
        dst[((size_t)b * H + h) * S + sidx] = acc;
    }
}

// ============================================================
// Kernel 2: attention via mma.sync + ldmatrix.
// Per CTA: one (b,h), 128 queries. 8 warps as 4(m)x2(n) -> 32q x 32d.
// P[128][64k] tf32 via exp (scores<=0 -> m=0 softmax), then O += P @ V.
// smem floats: Ksh[2048] | denp[256] | den[128] | Ps[128*68] | Vs[2*64*72]
// ============================================================
#define ATT_SMEM_FLOATS (2048 + 256 + 128 + 128*68 + 2*64*72)
#define ATT_SMEM_BYTES  (ATT_SMEM_FLOATS * 4)

__global__ __launch_bounds__(256) void attn_kernel()
{
    extern __shared__ float smem[];
    float* Ksh   = smem;              // 2048
    float* denp  = smem + 2048;       // 256
    float* den_s = smem + 2304;       // 128
    float* Ps    = smem + 2432;       // 128*68
    float* Vs    = smem + 11136;      // 2*64*72

    const int bh = blockIdx.y;
    const int b = bh >> 3, h = bh & 7;
    const int q0 = blockIdx.x * 128;
    const int tid = threadIdx.x;
    const int lane = tid & 31, wid = tid >> 5;
    const uint32_t sbase = smem_u32(smem);
    const uint32_t ps_addr = sbase + 2432u * 4u;
    const uint32_t vs_off  = 11136u * 4u;

    for (int i = tid; i < S; i += 256) Ksh[i] = g_K[(size_t)bh * S + i];

    // P-gen ownership: each thread: one query, 32 contiguous keys
    const int pq = tid >> 1;
    const int pk = (tid & 1) * 32;
    const float qv = g_Q[(size_t)bh * S + q0 + pq];
    float dpart = 0.f;

    const float* Vg = g_V + (size_t)b * S * E + h * D;
    auto loadV = [&](int kc, int buf) {
        #pragma unroll
        for (int p = 0; p < 4; p++) {
            const int r = (tid >> 4) + p * 16;
            const float* src = Vg + (size_t)(kc * 64 + r) * E + (tid & 15) * 4;
            const uint32_t dst = sbase + vs_off +
                (uint32_t)((buf * 4608 + r * 72 + (tid & 15) * 4) * 4);
            CP_ASYNC16(dst, src);
        }
    };

    loadV(0, 0);
    CP_COMMIT();
    __syncthreads();    // Ksh ready

    // mma-phase constants
    const int wm = wid >> 1;   // 0..3 -> q rows wm*32
    const int wn = wid & 1;    // 0..1 -> d cols wn*32
    const int mb = wm * 32;
    const int lrow  = (lane & 7) + ((lane >> 3) & 1) * 8;
    const int lkoff = ((lane >> 3) & 2) * 2;           // 0 or 4
    const uint32_t aAddr0 = ps_addr + (uint32_t)(((mb + lrow) * 68 + lkoff) * 4);
    const uint32_t aAddr1 = ps_addr + (uint32_t)(((mb + 16 + lrow) * 68 + lkoff) * 4);
    const int bk = lane & 3;
    const int bn = wn * 32 + (lane >> 2);

    float acc[2][4][4];
    #pragma unroll
    for (int i = 0; i < 2; i++)
        #pragma unroll
        for (int j = 0; j < 4; j++)
            #pragma unroll
            for (int l = 0; l < 4; l++) acc[i][j][l] = 0.f;

    const int NCH = S / 64;    // 32
    for (int kc = 0; kc < NCH; kc++) {
        const int buf = kc & 1;
        if (kc + 1 < NCH) { loadV(kc + 1, buf ^ 1); CP_COMMIT(); }
        // ---- P generation ----
        #pragma unroll 8
        for (int i = 0; i < 32; i++) {
            const int kk = pk + i;
            const float d = qv - Ksh[kc * 64 + kk];
            float w = __expf(-0.125f * d * d);
            w = round_tf32(w);
            dpart += w;
            Ps[pq * 68 + kk] = w;
        }
        if (kc + 1 < NCH) cp_wait<1>(); else cp_wait<0>();
        __syncthreads();
        // ---- O += P @ V ----
        const uint32_t* Vu = (const uint32_t*)(Vs + buf * 4608);
        #pragma unroll
        for (int ks = 0; ks < 8; ks++) {
            uint32_t a0[4], a1[4];
            ldsm_x4(a0, aAddr0 + ks * 32);
            ldsm_x4(a1, aAddr1 + ks * 32);
            const int k0 = ks * 8 + bk;
            #pragma unroll
            for (int nt = 0; nt < 4; nt++) {
                uint32_t bb[2] = { Vu[k0 * 72 + bn + nt * 8],
                                   Vu[(k0 + 4) * 72 + bn + nt * 8] };
                mma_tf32(acc[0][nt], a0, bb);
                mma_tf32(acc[1][nt], a1, bb);
            }
        }
        __syncthreads();
    }

    // denominator reduce: 2 partials per query
    denp[tid] = dpart;
    __syncthreads();
    if (tid < 128) den_s[tid] = 1.0f / (denp[tid * 2] + denp[tid * 2 + 1]);
    __syncthreads();

    // epilogue
    #pragma unroll
    for (int mt = 0; mt < 2; mt++) {
        const int r0 = wm * 32 + mt * 16 + (lane >> 2);
        const float inv0 = den_s[r0], inv1 = den_s[r0 + 8];
        #pragma unroll
        for (int nt = 0; nt < 4; nt++) {
            const int col = wn * 32 + nt * 8 + (lane & 3) * 2;
            float2 v0, v1;
            v0.x = round_tf32(acc[mt][nt][0] * inv0);
            v0.y = round_tf32(acc[mt][nt][1] * inv0);
            v1.x = round_tf32(acc[mt][nt][2] * inv1);
            v1.y = round_tf32(acc[mt][nt][3] * inv1);
            const size_t t0 = ((size_t)b * S + q0 + r0) * E + h * D + col;
            const size_t t1 = ((size_t)b * S + q0 + r0 + 8) * E + h * D + col;
            *(float2*)&g_HO[t0] = v0;
            *(float2*)&g_HO[t1] = v1;
        }
    }
}

// ============================================================
// Kernel 3/4: mma.sync tf32 GEMM, ldmatrix frags, 1 sync/chunk.
// 128x128 CTA tile, BK=32, 3-stage cp.async; warps 2(m)x4(n) = 64x32.
// smem elem (r,k) at r*32 + (k ^ ((r&7)<<2)) -- 16B-granular XOR swizzle.
// ============================================================
#define GEMM_SMEM_BYTES (3 * 8192 * 4)

template<int MODE>
__global__ __launch_bounds__(256) void tc_gemm_kernel(
    const float* __restrict__ Bt, const float* __restrict__ bias,
    const float* __restrict__ res, float* __restrict__ Cout,
    int N, int K)
{
    extern __shared__ float smem[];
    const float* A = (MODE == 0) ? g_HO : g_MID;
    float* C = (MODE == 0) ? g_MID : Cout;

    const int tid = threadIdx.x;
    const int lane = tid & 31, wid = tid >> 5;
    const int bm = blockIdx.y * 128;
    const int bn = blockIdx.x * 128;
    const int wm = wid >> 2;   // 0..1
    const int wn = wid & 3;    // 0..3
    const uint32_t sbase = smem_u32(smem);

    const int lr = tid >> 3;
    const int lg = tid & 7;

    auto load_tile = [&](int kc, int st) {
        #pragma unroll
        for (int p = 0; p < 4; p++) {
            const int r = lr + p * 32;
            const uint32_t sw = (uint32_t)((st * 8192 + r * 32 + ((lg ^ (r & 7)) * 4)) * 4);
            CP_ASYNC16(sbase + sw, A  + (size_t)(bm + r) * K + kc * 32 + lg * 4);
            CP_ASYNC16(sbase + sw + 4096u * 4u, Bt + (size_t)(bn + r) * K + kc * 32 + lg * 4);
        }
    };

    // ldmatrix constants
    const int lrow  = (lane & 7) + ((lane >> 3) & 1) * 8;
    const int lkoff = ((lane >> 3) & 2) * 2;            // A: 0/4
    const int cA = lkoff ^ ((lane & 7) * 4);            // k = (ks*8) ^ cA
    const int bnrow = wn * 32 + (lane & 7) + ((lane >> 3) >> 1) * 8;
    const int bkoff = ((lane >> 3) & 1) * 4;            // B: 0/4
    const int cB = bkoff ^ ((lane & 7) * 4);
    // byte row bases (k added per ks)
    uint32_t aRow[4];
    #pragma unroll
    for (int mt = 0; mt < 4; mt++)
        aRow[mt] = (uint32_t)((wm * 64 + mt * 16 + lrow) * 32 * 4);
    const uint32_t bRow0 = 4096u * 4u + (uint32_t)(bnrow * 32 * 4);
    const uint32_t bRow1 = bRow0 + 16u * 32u * 4u;

    float acc[4][4][4];
    #pragma unroll
    for (int i = 0; i < 4; i++)
        #pragma unroll
        for (int j = 0; j < 4; j++)
            #pragma unroll
            for (int l = 0; l < 4; l++) acc[i][j][l] = 0.f;

    const int nc = K / 32;
    load_tile(0, 0); CP_COMMIT();
    load_tile(1, 1); CP_COMMIT();

    for (int kc = 0; kc < nc; kc++) {
        const int st = kc % 3;
        if (kc + 1 < nc) cp_wait<1>(); else cp_wait<0>();
        __syncthreads();
        if (kc + 2 < nc) { load_tile(kc + 2, (kc + 2) % 3); CP_COMMIT(); }

        const uint32_t stb = sbase + (uint32_t)(st * 8192 * 4);
        #pragma unroll
        for (int ks = 0; ks < 4; ks++) {
            const uint32_t kA = (uint32_t)((((ks * 8) ^ cA)) * 4);
            const uint32_t kB = (uint32_t)((((ks * 8) ^ cB)) * 4);
            uint32_t a[4][4], b01[4], b23[4];
            #pragma unroll
            for (int mt = 0; mt < 4; mt++) ldsm_x4(a[mt], stb + aRow[mt] + kA);
            ldsm_x4(b01, stb + bRow0 + kB);
            ldsm_x4(b23, stb + bRow1 + kB);
            #pragma unroll
            for (int mt = 0; mt < 4; mt++) {
                mma_tf32(acc[mt][0], a[mt], b01);
                mma_tf32(acc[mt][1], a[mt], b01 + 2);
                mma_tf32(acc[mt][2], a[mt], b23);
                mma_tf32(acc[mt][3], a[mt], b23 + 2);
            }
        }
    }

    // epilogue
    #pragma unroll
    for (int mt = 0; mt < 4; mt++) {
        const int r0 = bm + wm * 64 + mt * 16 + (lane >> 2);
        #pragma unroll
        for (int nt = 0; nt < 4; nt++) {
            const int col = bn + wn * 32 + nt * 8 + (lane & 3) * 2;
            const float bz0 = bias[col], bz1 = bias[col + 1];
            float c0 = acc[mt][nt][0] + bz0;
            float c1 = acc[mt][nt][1] + bz1;
            float c2 = acc[mt][nt][2] + bz0;
            float c3 = acc[mt][nt][3] + bz1;
            const size_t g0 = (size_t)r0 * N + col;
            const size_t g1 = (size_t)(r0 + 8) * N + col;
            if (MODE == 0) {
                c0 = round_tf32(c0 * normcdff(c0));
                c1 = round_tf32(c1 * normcdff(c1));
                c2 = round_tf32(c2 * normcdff(c2));
                c3 = round_tf32(c3 * normcdff(c3));
            } else {
                c0 += res[g0]; c1 += res[g0 + 1];
                c2 += res[g1]; c3 += res[g1 + 1];
            }
            float2 v0; v0.x = c0; v0.y = c1;
            float2 v1; v1.x = c2; v1.y = c3;
            *(float2*)&C[g0] = v0;
            *(float2*)&C[g1] = v1;
        }
    }
}

// ============================================================
extern "C" void kernel_launch(void* const* d_in, const int* in_sizes, int n_in,
                              void* d_out, int out_size)
{
    const float* input1 = (const float*)d_in[0];
    const float* Wv = (const float*)d_in[1];
    const float* bv = (const float*)d_in[2];
    const float* Wq = (const float*)d_in[3];
    const float* bq = (const float*)d_in[4];
    const float* Wk = (const float*)d_in[5];
    const float* bk = (const float*)d_in[6];
    const float* W1 = (const float*)d_in[7];
    const float* b1 = (const float*)d_in[8];
    const float* W2 = (const float*)d_in[9];
    const float* b2 = (const float*)d_in[10];
    float* out = (float*)d_out;

    float* s_Wt1; cudaGetSymbolAddress((void**)&s_Wt1, g_Wt1);
    float* s_Wt2; cudaGetSymbolAddress((void**)&s_Wt2, g_Wt2);

    cudaFuncSetAttribute(attn_kernel, cudaFuncAttributeMaxDynamicSharedMemorySize, ATT_SMEM_BYTES);
    cudaFuncSetAttribute(tc_gemm_kernel<0>, cudaFuncAttributeMaxDynamicSharedMemorySize, GEMM_SMEM_BYTES);
    cudaFuncSetAttribute(tc_gemm_kernel<1>, cudaFuncAttributeMaxDynamicSharedMemorySize, GEMM_SMEM_BYTES);

    transpose_round_kernel<<<dim3(FF / 32, E / 32), 256>>>(W1, s_Wt1, E, FF);
    transpose_round_kernel<<<dim3(E / 32, FF / 32), 256>>>(W2, s_Wt2, FF, E);

    ln_proj_kernel<<<NTOK, 256>>>(input1, Wv, bv, Wq, bq, Wk, bk);
    attn_kernel<<<dim3(S / 128, B * H), 256, ATT_SMEM_BYTES>>>();

    tc_gemm_kernel<0><<<dim3(FF / 128, NTOK / 128), 256, GEMM_SMEM_BYTES>>>(s_Wt1, b1, nullptr, nullptr, FF, E);
    tc_gemm_kernel<1><<<dim3(E / 128, NTOK / 128), 256, GEMM_SMEM_BYTES>>>(s_Wt2, b2, input1, out, E, FF);
}